// round 9
// baseline (speedup 1.0000x reference)
#include <cuda_runtime.h>
#include <cstdint>

// ---------------- problem constants ----------------
constexpr int Tn   = 128;   // seq len
constexpr int Bq   = 256;   // batch
constexpr int Hh   = 512;   // hidden
constexpr int Ee   = 16;    // embed
constexpr int Ln   = 4;     // layers
constexpr int G4   = 2048;  // 4H

// K-permutation within each 16-block: k' = (k&3)*4 + (k>>2)
__host__ __device__ __forceinline__ int perm16(int k) {
    return (k & ~15) | (((k & 3) << 2) | ((k >> 2) & 3));
}

// ---------------- device scratch (static; no allocation) ----------------
// All K-dimensions stored PERMUTED by perm16. h is stored feature-permuted.
__device__ float d_Wih0[2 * G4 * Ee];
__device__ float d_Whh0[2 * G4 * Hh];
__device__ float d_WihL[3 * 2 * G4 * 1024];
__device__ float d_WhhL[3 * 2 * G4 * Hh];
__device__ float d_bias[Ln * 2 * G4];           // bih + bhh (unit-indexed, NOT permuted)
__device__ float d_x0[Tn * Bq * Ee];            // rounded embed[tokens], feature-permuted
__device__ float d_h[3][Ln * 2 * Bq * Hh];      // 3-deep ring, feature-permuted
__device__ float d_c[Ln * 2 * Bq * Hh];         // c state (unit-indexed, plain)

// ---------------- helpers ----------------
__device__ __forceinline__ float tf32r(float x) {
    uint32_t u;
    asm("cvt.rna.tf32.f32 %0, %1;" : "=r"(u) : "f"(x));
    return __uint_as_float(u);
}

__device__ __forceinline__ void cp16(float* dst, const float* src) {
    unsigned s = (unsigned)__cvta_generic_to_shared(dst);
    asm volatile("cp.async.cg.shared.global [%0], [%1], 16;\n" :: "r"(s), "l"(src));
}
__device__ __forceinline__ void cp_commit() { asm volatile("cp.async.commit_group;\n"); }
template <int N>
__device__ __forceinline__ void cp_wait() { asm volatile("cp.async.wait_group %0;\n" :: "n"(N)); }

__device__ __forceinline__ void mma_tf32(float* c,
                                         uint32_t a0, uint32_t a1, uint32_t a2, uint32_t a3,
                                         uint32_t b0, uint32_t b1) {
    asm volatile(
        "mma.sync.aligned.m16n8k8.row.col.f32.tf32.tf32.f32 "
        "{%0,%1,%2,%3},{%4,%5,%6,%7},{%8,%9},{%0,%1,%2,%3};\n"
        : "+f"(c[0]), "+f"(c[1]), "+f"(c[2]), "+f"(c[3])
        : "r"(a0), "r"(a1), "r"(a2), "r"(a3), "r"(b0), "r"(b1));
}

__device__ __forceinline__ float sigf(float x) { return 1.0f / (1.0f + __expf(-x)); }

// ---------------- init: tf32-round + K-permute weights, gather+permute x0, zero state ----------------
__global__ void init_kernel(const int* __restrict__ tokens, const float* __restrict__ embed,
                            const float* __restrict__ Wih0, const float* __restrict__ Whh0,
                            const float* __restrict__ bih0, const float* __restrict__ bhh0,
                            const float* __restrict__ Wih,  const float* __restrict__ Whh,
                            const float* __restrict__ bih,  const float* __restrict__ bhh) {
    const int idx0   = blockIdx.x * blockDim.x + threadIdx.x;
    const int stride = gridDim.x * blockDim.x;

    for (int i = idx0; i < 2 * G4 * Ee; i += stride) {
        int row = i / Ee, k = i % Ee;
        d_Wih0[row * Ee + perm16(k)] = tf32r(Wih0[i]);
    }
    for (int i = idx0; i < 2 * G4 * Hh; i += stride) {
        int row = i / Hh, k = i % Hh;
        d_Whh0[row * Hh + perm16(k)] = tf32r(Whh0[i]);
    }
    for (int i = idx0; i < 3 * 2 * G4 * 1024; i += stride) {
        int row = i / 1024, k = i % 1024;
        d_WihL[row * 1024 + perm16(k)] = tf32r(Wih[i]);
    }
    for (int i = idx0; i < 3 * 2 * G4 * Hh; i += stride) {
        int row = i / Hh, k = i % Hh;
        d_WhhL[row * Hh + perm16(k)] = tf32r(Whh[i]);
    }
    for (int i = idx0; i < Ln * 2 * G4; i += stride) {
        int l = i / (2 * G4), r = i % (2 * G4);
        d_bias[i] = (l == 0) ? (bih0[r] + bhh0[r])
                             : (bih[(l - 1) * 2 * G4 + r] + bhh[(l - 1) * 2 * G4 + r]);
    }
    for (int i = idx0; i < Tn * Bq * Ee; i += stride) {
        int t = i / (Bq * Ee);
        int rem = i % (Bq * Ee);
        int b = rem / Ee, e = rem % Ee;
        d_x0[t * Bq * Ee + b * Ee + perm16(e)] = tf32r(embed[tokens[t * Bq + b] * Ee + e]);
    }
    for (int i = idx0; i < Ln * 2 * Bq * Hh; i += stride) {
        d_h[0][i] = 0.f;
        d_h[1][i] = 0.f;
        d_h[2][i] = 0.f;   // t=0 reads hprev from ring slot 2 -> must be zero
        d_c[i]    = 0.f;
    }
}

// ---------------- one LSTM cell (t, l, dir): 64 batch x 16 hidden units per block ----------------
// C tile [64, 64]: 64 batch rows x (4 gates x 16 units). 4 warps, 2x2 grid of 32x32 tiles.
// smem: 4 stages x (A 64x16 + B 64x16), 16B groups XOR-swizzled by (row&3).
// Global K-layout is perm16'd so thread (g,tg)'s fragment {tg,tg+4,tg+8,tg+12} is one float4.
template <int KIN>
__device__ __forceinline__ void lstm_cell(int t, int l, int dir, float* smem) {
    constexpr int NIT = (KIN + Hh) / 16;
    const int tid = threadIdx.x;
    const int mt  = blockIdx.x;   // 0..3
    const int jt  = blockIdx.y;   // 0..31
    const int b0  = mt * 64, j0 = jt * 16;

    const int rb = (t + 2) % 3, wb = t % 3;
    const float* __restrict__ hprevD = d_h[rb] + (l * 2 + dir) * Bq * Hh;
    float* __restrict__       houtD  = d_h[wb] + (l * 2 + dir) * Bq * Hh;
    float* __restrict__       cstD   = d_c     + (l * 2 + dir) * Bq * Hh;
    const float* __restrict__ xbase  = (KIN == Ee) ? (d_x0 + t * Bq * Ee)
                                                   : (d_h[wb] + (l - 1) * 2 * Bq * Hh);
    const float* __restrict__ WihD   = (KIN == Ee) ? (d_Wih0 + dir * G4 * Ee)
                                                   : (d_WihL + ((l - 1) * 2 + dir) * G4 * 1024);
    const float* __restrict__ WhhD   = (KIN == Ee) ? (d_Whh0 + dir * G4 * Hh)
                                                   : (d_WhhL + ((l - 1) * 2 + dir) * G4 * Hh);

    const int lrow = tid >> 2, lgrp = tid & 3;   // writer: 32 rows x 4 groups per 128 threads

    auto load_stage = [&](int it, int buf) {
        const int k0 = it * 16;
        float* sA = smem + buf * 2048;
        float* sB = sA + 1024;
        #pragma unroll
        for (int q = 0; q < 2; ++q) {
            int row = lrow + q * 32;          // 0..63
            int kk  = k0 + lgrp * 4;          // permuted-storage k index (16B group)
            int sw  = ((lgrp ^ (row & 3)) << 2);
            // A tile
            const float* srcA;
            int abg = b0 + row;
            if (kk < KIN) {
                if (KIN == Ee) srcA = xbase + abg * Ee + kk;
                else           srcA = xbase + ((kk >> 9) * Bq + abg) * Hh + (kk & 511);
            } else {
                srcA = hprevD + abg * Hh + (kk - KIN);
            }
            cp16(&sA[row * 16 + sw], srcA);
            // B tile: col n=row -> W row (n/16)*512 + j0 + n%16
            int wrow = (row >> 4) * Hh + j0 + (row & 15);
            const float* srcB = (kk < KIN) ? (WihD + wrow * KIN + kk)
                                           : (WhhD + wrow * Hh + (kk - KIN));
            cp16(&sB[row * 16 + sw], srcB);
        }
        cp_commit();
    };

    const int lane = tid & 31, wid = tid >> 5;
    const int wm = wid & 1, wn = wid >> 1;     // 2x2 warp grid, 32x32 warp tile
    const int g = lane >> 2, tg = lane & 3;

    float acc[2][4][4];
    #pragma unroll
    for (int i = 0; i < 2; i++)
        #pragma unroll
        for (int j = 0; j < 4; j++)
            #pragma unroll
            for (int k = 0; k < 4; k++) acc[i][j][k] = 0.f;

    load_stage(0, 0);
    if (NIT > 1) load_stage(1, 1);
    if (NIT > 2) load_stage(2, 2);
    for (int it = 0; it < NIT; ++it) {
        const int ahead = NIT - 1 - it;
        if      (ahead >= 2) cp_wait<2>();
        else if (ahead == 1) cp_wait<1>();
        else                 cp_wait<0>();
        __syncthreads();
        if (it + 3 < NIT) load_stage(it + 3, (it + 3) & 3);
        const float* A  = smem + (it & 3) * 2048;
        const float* Bs = A + 1024;

        // fragment loads: one LDS.128 per (row, 16-k) — XOR-swizzled group
        float4 bv[4];
        #pragma unroll
        for (int ni = 0; ni < 4; ++ni) {
            int n = wn * 32 + ni * 8 + g;
            bv[ni] = *reinterpret_cast<const float4*>(Bs + n * 16 + ((tg ^ (n & 3)) << 2));
        }
        #pragma unroll
        for (int mi = 0; mi < 2; ++mi) {
            int r = wm * 32 + mi * 16 + g;
            float4 a0 = *reinterpret_cast<const float4*>(A + r * 16 + ((tg ^ (r & 3)) << 2));
            float4 a1 = *reinterpret_cast<const float4*>(A + (r + 8) * 16 + ((tg ^ (r & 3)) << 2));
            #pragma unroll
            for (int ni = 0; ni < 4; ++ni) {
                // kc = 0 uses (x=k[tg], y=k[tg+4]); kc = 8 uses (z=k[tg+8], w=k[tg+12])
                mma_tf32(acc[mi][ni],
                         __float_as_uint(a0.x), __float_as_uint(a1.x),
                         __float_as_uint(a0.y), __float_as_uint(a1.y),
                         __float_as_uint(bv[ni].x), __float_as_uint(bv[ni].y));
                mma_tf32(acc[mi][ni],
                         __float_as_uint(a0.z), __float_as_uint(a1.z),
                         __float_as_uint(a0.w), __float_as_uint(a1.w),
                         __float_as_uint(bv[ni].z), __float_as_uint(bv[ni].w));
            }
        }
    }
    __syncthreads();   // all reads of stage buffers done before reuse as gt

    // ---- epilogue: restage gates to smem gt[64][80] ----
    float* gt = smem;
    #pragma unroll
    for (int mi = 0; mi < 2; ++mi)
        #pragma unroll
        for (int ni = 0; ni < 4; ++ni) {
            int r  = wm * 32 + mi * 16 + g;
            int cc = wn * 32 + ni * 8 + 2 * tg;
            gt[r * 80 + cc]           = acc[mi][ni][0];
            gt[r * 80 + cc + 1]       = acc[mi][ni][1];
            gt[(r + 8) * 80 + cc]     = acc[mi][ni][2];
            gt[(r + 8) * 80 + cc + 1] = acc[mi][ni][3];
        }
    __syncthreads();

    // elementwise LSTM cell update: 64 rows x 16 units, 8 cells/thread
    const int jj = tid & 15;           // unit within tile
    const int rbase = tid >> 4;        // 0..7
    const float* biasD = d_bias + (l * 2 + dir) * G4;
    const int j = j0 + jj;
    const float bi = biasD[0 * Hh + j];
    const float bf = biasD[1 * Hh + j];
    const float bg = biasD[2 * Hh + j];
    const float bo = biasD[3 * Hh + j];
    const int jp = j0 + (((jj & 3) << 2) | (jj >> 2));   // perm16'd h storage position
    #pragma unroll
    for (int q = 0; q < 8; ++q) {
        int row = rbase + q * 8;       // 0..63
        int b = b0 + row;
        float gi = gt[row * 80 +  0 + jj] + bi;
        float gf = gt[row * 80 + 16 + jj] + bf;
        float gg = gt[row * 80 + 32 + jj] + bg;
        float go = gt[row * 80 + 48 + jj] + bo;
        float i_ = sigf(gi), f_ = sigf(gf), g_ = tanhf(gg), o_ = sigf(go);
        float cn = fmaf(f_, cstD[b * Hh + j], i_ * g_);
        cstD[b * Hh + j]   = cn;
        houtD[b * Hh + jp] = tf32r(o_ * tanhf(cn));   // permuted store; tf32 pre-round (rna)
    }
}

// ---------------- wavefront kernel ----------------
// grid = (4 mtiles, 32 jtiles, ncells*2); blockIdx.z = (cell_idx << 1) | dir
__global__ __launch_bounds__(128, 7) void lstm_wave(int w, int lmin) {
    __shared__ __align__(16) float smem[8192];   // 4 stages x 2048 floats = 32 KB
    const int cell = blockIdx.z >> 1;
    const int dir  = blockIdx.z & 1;
    const int l    = lmin + cell;
    const int t    = w - l;
    if (t < 0 || t >= Tn) return;
    if (l == 0) lstm_cell<Ee>(t, 0, dir, smem);
    else        lstm_cell<1024>(t, l, dir, smem);
}

// ---------------- final FC + softmax ----------------
__global__ __launch_bounds__(256) void fc_softmax(const float* __restrict__ fcw,
                                                  const float* __restrict__ fcb,
                                                  float* __restrict__ out) {
    const int b = blockIdx.x;
    const int tid = threadIdx.x, lane = tid & 31, w = tid >> 5;
    __shared__ float sv[64];
    const float* __restrict__ hf = d_h[(Tn - 1) % 3];   // t=127 wrote ring slot 1
    float acc[8] = {0, 0, 0, 0, 0, 0, 0, 0};
    for (int k = lane; k < 8192; k += 32) {
        int s = k >> 10, r = k & 1023;
        int j = r & 511;
        float hv = (r & 512) ? d_c[(s * Bq + b) * Hh + j]
                             : hf[(s * Bq + b) * Hh + perm16(j)];   // h stored permuted
        #pragma unroll
        for (int q = 0; q < 8; ++q)
            acc[q] = fmaf(hv, fcw[(w * 8 + q) * 8192 + k], acc[q]);
    }
    #pragma unroll
    for (int q = 0; q < 8; ++q) {
        float v = acc[q];
        #pragma unroll
        for (int off = 16; off; off >>= 1) v += __shfl_xor_sync(0xffffffffu, v, off);
        if (lane == 0) sv[w * 8 + q] = v + fcb[w * 8 + q];
    }
    __syncthreads();
    if (tid < 32) {
        float v0 = sv[tid], v1 = sv[tid + 32];
        float m = fmaxf(v0, v1);
        #pragma unroll
        for (int off = 16; off; off >>= 1) m = fmaxf(m, __shfl_xor_sync(0xffffffffu, m, off));
        float e0 = expf(v0 - m), e1 = expf(v1 - m);
        float s = e0 + e1;
        #pragma unroll
        for (int off = 16; off; off >>= 1) s += __shfl_xor_sync(0xffffffffu, s, off);
        float inv = 1.0f / s;
        out[b * 64 + tid]      = e0 * inv;
        out[b * 64 + 32 + tid] = e1 * inv;
    }
}

// ---------------- launch ----------------
extern "C" void kernel_launch(void* const* d_in, const int* in_sizes, int n_in,
                              void* d_out, int out_size) {
    const int*   tokens = (const int*)  d_in[0];
    const float* embed  = (const float*)d_in[1];
    const float* Wih0   = (const float*)d_in[2];
    const float* Whh0   = (const float*)d_in[3];
    const float* bih0   = (const float*)d_in[4];
    const float* bhh0   = (const float*)d_in[5];
    const float* Wih    = (const float*)d_in[6];
    const float* Whh    = (const float*)d_in[7];
    const float* bih    = (const float*)d_in[8];
    const float* bhh    = (const float*)d_in[9];
    const float* fcw    = (const float*)d_in[10];
    const float* fcb    = (const float*)d_in[11];
    float*       out    = (float*)d_out;

    init_kernel<<<512, 256>>>(tokens, embed, Wih0, Whh0, bih0, bhh0, Wih, Whh, bih, bhh);

    // wavefront schedule: cells (t, l) with t + l == w are independent
    for (int w = 0; w <= (Tn - 1) + (Ln - 1); ++w) {
        int lmin = max(0, w - (Tn - 1));
        int lmax = min(Ln - 1, w);
        int ncells = lmax - lmin + 1;
        dim3 grid(4, 32, ncells * 2);
        lstm_wave<<<grid, 128>>>(w, lmin);
    }
    fc_softmax<<<Bq, 256>>>(fcw, fcb, out);
}

// round 11
// speedup vs baseline: 1.0243x; 1.0243x over previous
#include <cuda_runtime.h>
#include <cstdint>

// ---------------- problem constants ----------------
constexpr int Tn   = 128;   // seq len
constexpr int Bq   = 256;   // batch
constexpr int Hh   = 512;   // hidden
constexpr int Ee   = 16;    // embed
constexpr int Ln   = 4;     // layers
constexpr int G4   = 2048;  // 4H

// K-permutation within each 16-block: k' = (k&3)*4 + (k>>2)
__host__ __device__ __forceinline__ int perm16(int k) {
    return (k & ~15) | (((k & 3) << 2) | ((k >> 2) & 3));
}

// ---------------- device scratch (static; no allocation) ----------------
// All K-dimensions stored PERMUTED by perm16. h is stored feature-permuted.
__device__ float d_Wih0[2 * G4 * Ee];
__device__ float d_Whh0[2 * G4 * Hh];
__device__ float d_WihL[3 * 2 * G4 * 1024];
__device__ float d_WhhL[3 * 2 * G4 * Hh];
__device__ float d_bias[Ln * 2 * G4];           // bih + bhh (unit-indexed, NOT permuted)
__device__ float d_x0[Tn * Bq * Ee];            // rounded embed[tokens], feature-permuted
__device__ float d_h[3][Ln * 2 * Bq * Hh];      // 3-deep ring, feature-permuted
__device__ float d_c[Ln * 2 * Bq * Hh];         // c state (unit-indexed, plain)

// ---------------- helpers ----------------
__device__ __forceinline__ float tf32r(float x) {
    uint32_t u;
    asm("cvt.rna.tf32.f32 %0, %1;" : "=r"(u) : "f"(x));
    return __uint_as_float(u);
}

__device__ __forceinline__ void cp16(float* dst, const float* src) {
    unsigned s = (unsigned)__cvta_generic_to_shared(dst);
    asm volatile("cp.async.cg.shared.global [%0], [%1], 16;\n" :: "r"(s), "l"(src));
}
__device__ __forceinline__ void cp_commit() { asm volatile("cp.async.commit_group;\n"); }
template <int N>
__device__ __forceinline__ void cp_wait() { asm volatile("cp.async.wait_group %0;\n" :: "n"(N)); }

__device__ __forceinline__ void mma_tf32(float* c,
                                         uint32_t a0, uint32_t a1, uint32_t a2, uint32_t a3,
                                         uint32_t b0, uint32_t b1) {
    asm volatile(
        "mma.sync.aligned.m16n8k8.row.col.f32.tf32.tf32.f32 "
        "{%0,%1,%2,%3},{%4,%5,%6,%7},{%8,%9},{%0,%1,%2,%3};\n"
        : "+f"(c[0]), "+f"(c[1]), "+f"(c[2]), "+f"(c[3])
        : "r"(a0), "r"(a1), "r"(a2), "r"(a3), "r"(b0), "r"(b1));
}

__device__ __forceinline__ float sigf(float x) { return 1.0f / (1.0f + __expf(-x)); }

// ---------------- init: tf32-round + K-permute weights, gather+permute x0, zero state ----------------
__global__ void init_kernel(const int* __restrict__ tokens, const float* __restrict__ embed,
                            const float* __restrict__ Wih0, const float* __restrict__ Whh0,
                            const float* __restrict__ bih0, const float* __restrict__ bhh0,
                            const float* __restrict__ Wih,  const float* __restrict__ Whh,
                            const float* __restrict__ bih,  const float* __restrict__ bhh) {
    const int idx0   = blockIdx.x * blockDim.x + threadIdx.x;
    const int stride = gridDim.x * blockDim.x;

    for (int i = idx0; i < 2 * G4 * Ee; i += stride) {
        int row = i / Ee, k = i % Ee;
        d_Wih0[row * Ee + perm16(k)] = tf32r(Wih0[i]);
    }
    for (int i = idx0; i < 2 * G4 * Hh; i += stride) {
        int row = i / Hh, k = i % Hh;
        d_Whh0[row * Hh + perm16(k)] = tf32r(Whh0[i]);
    }
    for (int i = idx0; i < 3 * 2 * G4 * 1024; i += stride) {
        int row = i / 1024, k = i % 1024;
        d_WihL[row * 1024 + perm16(k)] = tf32r(Wih[i]);
    }
    for (int i = idx0; i < 3 * 2 * G4 * Hh; i += stride) {
        int row = i / Hh, k = i % Hh;
        d_WhhL[row * Hh + perm16(k)] = tf32r(Whh[i]);
    }
    for (int i = idx0; i < Ln * 2 * G4; i += stride) {
        int l = i / (2 * G4), r = i % (2 * G4);
        d_bias[i] = (l == 0) ? (bih0[r] + bhh0[r])
                             : (bih[(l - 1) * 2 * G4 + r] + bhh[(l - 1) * 2 * G4 + r]);
    }
    for (int i = idx0; i < Tn * Bq * Ee; i += stride) {
        int t = i / (Bq * Ee);
        int rem = i % (Bq * Ee);
        int b = rem / Ee, e = rem % Ee;
        d_x0[t * Bq * Ee + b * Ee + perm16(e)] = tf32r(embed[tokens[t * Bq + b] * Ee + e]);
    }
    for (int i = idx0; i < Ln * 2 * Bq * Hh; i += stride) {
        d_h[0][i] = 0.f;
        d_h[1][i] = 0.f;
        d_h[2][i] = 0.f;   // t=0 reads hprev from ring slot 2 -> must be zero
        d_c[i]    = 0.f;
    }
}

// ---------------- one LSTM cell (t, l, dir): 64 batch x 32 hidden units per block ----------------
// C tile [64, 128]: 64 batch rows x (4 gates x 32 units). 4 warps, 2x2 grid of 32x64 warp tiles.
// smem: 4 stages x (A 64x16 + B 128x16), 16B groups XOR-swizzled by (row&3).
// Global K-layout is perm16'd so thread (g,tg)'s fragment {tg,tg+4,tg+8,tg+12} is one float4.
template <int KIN>
__device__ __forceinline__ void lstm_cell(int t, int l, int dir, float* smem) {
    constexpr int NIT = (KIN + Hh) / 16;
    const int tid = threadIdx.x;
    const int mt  = blockIdx.x;   // 0..3
    const int jt  = blockIdx.y;   // 0..15
    const int b0  = mt * 64, j0 = jt * 32;

    const int rb = (t + 2) % 3, wb = t % 3;
    const float* __restrict__ hprevD = d_h[rb] + (l * 2 + dir) * Bq * Hh;
    float* __restrict__       houtD  = d_h[wb] + (l * 2 + dir) * Bq * Hh;
    float* __restrict__       cstD   = d_c     + (l * 2 + dir) * Bq * Hh;
    const float* __restrict__ xbase  = (KIN == Ee) ? (d_x0 + t * Bq * Ee)
                                                   : (d_h[wb] + (l - 1) * 2 * Bq * Hh);
    const float* __restrict__ WihD   = (KIN == Ee) ? (d_Wih0 + dir * G4 * Ee)
                                                   : (d_WihL + ((l - 1) * 2 + dir) * G4 * 1024);
    const float* __restrict__ WhhD   = (KIN == Ee) ? (d_Whh0 + dir * G4 * Hh)
                                                   : (d_WhhL + ((l - 1) * 2 + dir) * G4 * Hh);

    // ---- hoisted cp.async geometry ----
    // A: 256 slots (64 rows x 4 groups): slot = tid + q*128, q=0..1
    // B: 512 slots (128 rows x 4 groups): slot = tid + q*128, q=0..3
    const int grp = tid & 3;
    uint32_t aSm[2];  int aRow[2];          // smem float-offset; gmem row (batch)
    uint32_t bSm[4];  int bIh[4], bHh[4];   // smem float-offset; gmem row offsets
    #pragma unroll
    for (int q = 0; q < 2; ++q) {
        int slot = tid + q * 128, row = slot >> 2;
        aSm[q]  = row * 16 + (((slot & 3) ^ (row & 3)) << 2);
        aRow[q] = b0 + row;
    }
    #pragma unroll
    for (int q = 0; q < 4; ++q) {
        int slot = tid + q * 128, row = slot >> 2;
        int wrow = (row >> 5) * Hh + j0 + (row & 31);      // gate*512 + j0 + unit
        bSm[q]  = row * 16 + (((slot & 3) ^ (row & 3)) << 2);
        bIh[q]  = wrow * KIN + (slot & 3) * 4;
        bHh[q]  = wrow * Hh + (slot & 3) * 4;
    }

    auto load_stage = [&](int it, int buf) {
        const int k0 = it * 16;
        const int kk = k0 + grp * 4;
        float* sA = smem + buf * 3072;
        float* sB = sA + 1024;
        if (kk < KIN) {
            const float* ab = (KIN == Ee) ? xbase : (xbase + (kk >> 9) * Bq * Hh);
            const int ks = (KIN == Ee) ? kk : (kk & 511);
            const int as = (KIN == Ee) ? Ee : Hh;
            #pragma unroll
            for (int q = 0; q < 2; ++q) cp16(&sA[aSm[q]], ab + aRow[q] * as + ks);
            #pragma unroll
            for (int q = 0; q < 4; ++q) cp16(&sB[bSm[q]], WihD + bIh[q] + k0);
        } else {
            const int ko = kk - KIN;
            #pragma unroll
            for (int q = 0; q < 2; ++q) cp16(&sA[aSm[q]], hprevD + aRow[q] * Hh + ko);
            #pragma unroll
            for (int q = 0; q < 4; ++q) cp16(&sB[bSm[q]], WhhD + bHh[q] + (k0 - KIN));
        }
        cp_commit();
    };

    const int lane = tid & 31, wid = tid >> 5;
    const int wm = wid & 1, wn = wid >> 1;     // 2x2 warp grid, 32x64 warp tile
    const int g = lane >> 2, tg = lane & 3;
    const uint32_t asw = ((tg ^ (g & 3)) << 2);   // r&3 == g&3 for all fragment rows

    float acc[2][8][4];
    #pragma unroll
    for (int i = 0; i < 2; i++)
        #pragma unroll
        for (int j = 0; j < 8; j++)
            #pragma unroll
            for (int k = 0; k < 4; k++) acc[i][j][k] = 0.f;

    load_stage(0, 0);
    if (NIT > 1) load_stage(1, 1);
    if (NIT > 2) load_stage(2, 2);
    for (int it = 0; it < NIT; ++it) {
        const int ahead = NIT - 1 - it;
        if      (ahead >= 2) cp_wait<2>();
        else if (ahead == 1) cp_wait<1>();
        else                 cp_wait<0>();
        __syncthreads();
        if (it + 3 < NIT) load_stage(it + 3, (it + 3) & 3);
        const float* A  = smem + (it & 3) * 3072;
        const float* Bs = A + 1024;

        #pragma unroll
        for (int half = 0; half < 2; ++half) {
            float4 bv[4];
            #pragma unroll
            for (int n4 = 0; n4 < 4; ++n4) {
                int n = wn * 64 + half * 32 + n4 * 8 + g;
                bv[n4] = *reinterpret_cast<const float4*>(Bs + n * 16 + ((tg ^ (n & 3)) << 2));
            }
            #pragma unroll
            for (int mi = 0; mi < 2; ++mi) {
                int r = wm * 32 + mi * 16 + g;
                float4 a0 = *reinterpret_cast<const float4*>(A + r * 16 + asw);
                float4 a1 = *reinterpret_cast<const float4*>(A + (r + 8) * 16 + asw);
                #pragma unroll
                for (int n4 = 0; n4 < 4; ++n4) {
                    float* ac = acc[mi][half * 4 + n4];
                    mma_tf32(ac,
                             __float_as_uint(a0.x), __float_as_uint(a1.x),
                             __float_as_uint(a0.y), __float_as_uint(a1.y),
                             __float_as_uint(bv[n4].x), __float_as_uint(bv[n4].y));
                    mma_tf32(ac,
                             __float_as_uint(a0.z), __float_as_uint(a1.z),
                             __float_as_uint(a0.w), __float_as_uint(a1.w),
                             __float_as_uint(bv[n4].z), __float_as_uint(bv[n4].w));
                }
            }
        }
    }
    __syncthreads();   // all reads of stage buffers done before reuse as gt

    // ---- epilogue: restage gates to smem gt[64][132] ----
    float* gt = smem;
    #pragma unroll
    for (int mi = 0; mi < 2; ++mi)
        #pragma unroll
        for (int ni = 0; ni < 8; ++ni) {
            int r  = wm * 32 + mi * 16 + g;
            int cc = wn * 64 + ni * 8 + 2 * tg;
            gt[r * 132 + cc]           = acc[mi][ni][0];
            gt[r * 132 + cc + 1]       = acc[mi][ni][1];
            gt[(r + 8) * 132 + cc]     = acc[mi][ni][2];
            gt[(r + 8) * 132 + cc + 1] = acc[mi][ni][3];
        }
    __syncthreads();

    // elementwise LSTM cell update: 64 rows x 32 units, 16 cells/thread
    const int jj = tid & 31;           // unit within tile
    const int rbase = tid >> 5;        // 0..3
    const float* biasD = d_bias + (l * 2 + dir) * G4;
    const int j  = j0 + jj;
    const int jp = perm16(j);          // perm16'd h storage position
    const float bi = biasD[0 * Hh + j];
    const float bf = biasD[1 * Hh + j];
    const float bg = biasD[2 * Hh + j];
    const float bo = biasD[3 * Hh + j];
    #pragma unroll
    for (int q = 0; q < 16; ++q) {
        int row = rbase + q * 4;       // 0..63
        int b = b0 + row;
        float gi = gt[row * 132 +  0 + jj] + bi;
        float gf = gt[row * 132 + 32 + jj] + bf;
        float gg = gt[row * 132 + 64 + jj] + bg;
        float go = gt[row * 132 + 96 + jj] + bo;
        float i_ = sigf(gi), f_ = sigf(gf), g_ = tanhf(gg), o_ = sigf(go);
        float cn = fmaf(f_, cstD[b * Hh + j], i_ * g_);
        cstD[b * Hh + j]   = cn;
        houtD[b * Hh + jp] = tf32r(o_ * tanhf(cn));   // permuted store; tf32 pre-round (rna)
    }
}

// ---------------- wavefront kernel ----------------
// grid = (4 mtiles, 16 jtiles, ncells*2); blockIdx.z = (cell_idx << 1) | dir
__global__ __launch_bounds__(128, 4) void lstm_wave(int w, int lmin) {
    __shared__ __align__(16) float smem[12288];   // 4 stages x 3072 floats = 48 KB
    const int cell = blockIdx.z >> 1;
    const int dir  = blockIdx.z & 1;
    const int l    = lmin + cell;
    const int t    = w - l;
    if (t < 0 || t >= Tn) return;
    if (l == 0) lstm_cell<Ee>(t, 0, dir, smem);
    else        lstm_cell<1024>(t, l, dir, smem);
}

// ---------------- final FC + softmax ----------------
__global__ __launch_bounds__(256) void fc_softmax(const float* __restrict__ fcw,
                                                  const float* __restrict__ fcb,
                                                  float* __restrict__ out) {
    const int b = blockIdx.x;
    const int tid = threadIdx.x, lane = tid & 31, w = tid >> 5;
    __shared__ float sv[64];
    const float* __restrict__ hf = d_h[(Tn - 1) % 3];   // t=127 wrote ring slot 1
    float acc[8] = {0, 0, 0, 0, 0, 0, 0, 0};
    for (int k = lane; k < 8192; k += 32) {
        int s = k >> 10, r = k & 1023, j = r & 511;
        float hv = (r & 512) ? d_c[(s * Bq + b) * Hh + j]
                             : hf[(s * Bq + b) * Hh + perm16(j)];   // h stored permuted
        #pragma unroll
        for (int q = 0; q < 8; ++q)
            acc[q] = fmaf(hv, fcw[(w * 8 + q) * 8192 + k], acc[q]);
    }
    #pragma unroll
    for (int q = 0; q < 8; ++q) {
        float v = acc[q];
        #pragma unroll
        for (int off = 16; off; off >>= 1) v += __shfl_xor_sync(0xffffffffu, v, off);
        if (lane == 0) sv[w * 8 + q] = v + fcb[w * 8 + q];
    }
    __syncthreads();
    if (tid < 32) {
        float v0 = sv[tid], v1 = sv[tid + 32];
        float m = fmaxf(v0, v1);
        #pragma unroll
        for (int off = 16; off; off >>= 1) m = fmaxf(m, __shfl_xor_sync(0xffffffffu, m, off));
        float e0 = expf(v0 - m), e1 = expf(v1 - m);
        float s = e0 + e1;
        #pragma unroll
        for (int off = 16; off; off >>= 1) s += __shfl_xor_sync(0xffffffffu, s, off);
        float inv = 1.0f / s;
        out[b * 64 + tid]      = e0 * inv;
        out[b * 64 + 32 + tid] = e1 * inv;
    }
}

// ---------------- launch ----------------
extern "C" void kernel_launch(void* const* d_in, const int* in_sizes, int n_in,
                              void* d_out, int out_size) {
    const int*   tokens = (const int*)  d_in[0];
    const float* embed  = (const float*)d_in[1];
    const float* Wih0   = (const float*)d_in[2];
    const float* Whh0   = (const float*)d_in[3];
    const float* bih0   = (const float*)d_in[4];
    const float* bhh0   = (const float*)d_in[5];
    const float* Wih    = (const float*)d_in[6];
    const float* Whh    = (const float*)d_in[7];
    const float* bih    = (const float*)d_in[8];
    const float* bhh    = (const float*)d_in[9];
    const float* fcw    = (const float*)d_in[10];
    const float* fcb    = (const float*)d_in[11];
    float*       out    = (float*)d_out;

    init_kernel<<<512, 256>>>(tokens, embed, Wih0, Whh0, bih0, bhh0, Wih, Whh, bih, bhh);

    // wavefront schedule: cells (t, l) with t + l == w are independent
    for (int w = 0; w <= (Tn - 1) + (Ln - 1); ++w) {
        int lmin = max(0, w - (Tn - 1));
        int lmax = min(Ln - 1, w);
        int ncells = lmax - lmin + 1;
        dim3 grid(4, 16, ncells * 2);
        lstm_wave<<<grid, 128>>>(w, lmin);
    }
    fc_softmax<<<Bq, 256>>>(fcw, fcb, out);
}

// round 12
// speedup vs baseline: 1.1894x; 1.1611x over previous
#include <cuda_runtime.h>
#include <cstdint>

// ---------------- problem constants ----------------
constexpr int Tn   = 128;   // seq len
constexpr int Bq   = 256;   // batch
constexpr int Hh   = 512;   // hidden
constexpr int Ee   = 16;    // embed
constexpr int Ln   = 4;     // layers
constexpr int G4   = 2048;  // 4H

// K-permutation within each 16-block: k' = (k&3)*4 + (k>>2)
__host__ __device__ __forceinline__ int perm16(int k) {
    return (k & ~15) | (((k & 3) << 2) | ((k >> 2) & 3));
}

// ---------------- device scratch (static; no allocation) ----------------
// All K-dimensions stored PERMUTED by perm16. h is stored feature-permuted.
__device__ float d_Wih0[2 * G4 * Ee];
__device__ float d_Whh0[2 * G4 * Hh];
__device__ float d_WihL[3 * 2 * G4 * 1024];
__device__ float d_WhhL[3 * 2 * G4 * Hh];
__device__ float d_bias[Ln * 2 * G4];           // bih + bhh (unit-indexed, NOT permuted)
__device__ float d_x0[Tn * Bq * Ee];            // rounded embed[tokens], feature-permuted
__device__ float d_h[3][Ln * 2 * Bq * Hh];      // 3-deep ring, feature-permuted
__device__ float d_c[Ln * 2 * Bq * Hh];         // c state (unit-indexed, plain)

// ---------------- helpers ----------------
__device__ __forceinline__ float tf32r(float x) {
    uint32_t u;
    asm("cvt.rna.tf32.f32 %0, %1;" : "=r"(u) : "f"(x));
    return __uint_as_float(u);
}

__device__ __forceinline__ void cp16(float* dst, const float* src) {
    unsigned s = (unsigned)__cvta_generic_to_shared(dst);
    asm volatile("cp.async.cg.shared.global [%0], [%1], 16;\n" :: "r"(s), "l"(src));
}
__device__ __forceinline__ void cp_commit() { asm volatile("cp.async.commit_group;\n"); }
template <int N>
__device__ __forceinline__ void cp_wait() { asm volatile("cp.async.wait_group %0;\n" :: "n"(N)); }

__device__ __forceinline__ void mma_tf32(float* c,
                                         uint32_t a0, uint32_t a1, uint32_t a2, uint32_t a3,
                                         uint32_t b0, uint32_t b1) {
    asm volatile(
        "mma.sync.aligned.m16n8k8.row.col.f32.tf32.tf32.f32 "
        "{%0,%1,%2,%3},{%4,%5,%6,%7},{%8,%9},{%0,%1,%2,%3};\n"
        : "+f"(c[0]), "+f"(c[1]), "+f"(c[2]), "+f"(c[3])
        : "r"(a0), "r"(a1), "r"(a2), "r"(a3), "r"(b0), "r"(b1));
}

__device__ __forceinline__ float sigf(float x) { return 1.0f / (1.0f + __expf(-x)); }

// ---------------- init: tf32-round + K-permute weights, gather+permute x0, zero state ----------------
__global__ void init_kernel(const int* __restrict__ tokens, const float* __restrict__ embed,
                            const float* __restrict__ Wih0, const float* __restrict__ Whh0,
                            const float* __restrict__ bih0, const float* __restrict__ bhh0,
                            const float* __restrict__ Wih,  const float* __restrict__ Whh,
                            const float* __restrict__ bih,  const float* __restrict__ bhh) {
    const int idx0   = blockIdx.x * blockDim.x + threadIdx.x;
    const int stride = gridDim.x * blockDim.x;

    for (int i = idx0; i < 2 * G4 * Ee; i += stride) {
        int row = i / Ee, k = i % Ee;
        d_Wih0[row * Ee + perm16(k)] = tf32r(Wih0[i]);
    }
    for (int i = idx0; i < 2 * G4 * Hh; i += stride) {
        int row = i / Hh, k = i % Hh;
        d_Whh0[row * Hh + perm16(k)] = tf32r(Whh0[i]);
    }
    for (int i = idx0; i < 3 * 2 * G4 * 1024; i += stride) {
        int row = i / 1024, k = i % 1024;
        d_WihL[row * 1024 + perm16(k)] = tf32r(Wih[i]);
    }
    for (int i = idx0; i < 3 * 2 * G4 * Hh; i += stride) {
        int row = i / Hh, k = i % Hh;
        d_WhhL[row * Hh + perm16(k)] = tf32r(Whh[i]);
    }
    for (int i = idx0; i < Ln * 2 * G4; i += stride) {
        int l = i / (2 * G4), r = i % (2 * G4);
        d_bias[i] = (l == 0) ? (bih0[r] + bhh0[r])
                             : (bih[(l - 1) * 2 * G4 + r] + bhh[(l - 1) * 2 * G4 + r]);
    }
    for (int i = idx0; i < Tn * Bq * Ee; i += stride) {
        int t = i / (Bq * Ee);
        int rem = i % (Bq * Ee);
        int b = rem / Ee, e = rem % Ee;
        d_x0[t * Bq * Ee + b * Ee + perm16(e)] = tf32r(embed[tokens[t * Bq + b] * Ee + e]);
    }
    for (int i = idx0; i < Ln * 2 * Bq * Hh; i += stride) {
        d_h[0][i] = 0.f;
        d_h[1][i] = 0.f;
        d_h[2][i] = 0.f;   // t=0 reads hprev from ring slot 2 -> must be zero
        d_c[i]    = 0.f;
    }
}

// ---------------- one LSTM cell (t, l, dir): 64 batch x 16 hidden units per block ----------------
// C tile [64, 64]: 64 batch rows x (4 gates x 16 units). 4 warps, 2x2 grid of 32x32 tiles.
// smem: 3 stages x (A 64x16 + B 64x16) = 24 KB -> 7 blocks/SM; full wave (1024 blocks)
// is single-residency (7 x 148 = 1036). One __syncthreads per K-iter:
// at iter it, load stage (it+2)%3, whose last reader was iter it-1 (protected by this barrier).
template <int KIN>
__device__ __forceinline__ void lstm_cell(int t, int l, int dir, float* smem) {
    constexpr int NIT = (KIN + Hh) / 16;
    const int tid = threadIdx.x;
    const int mt  = blockIdx.x;   // 0..3
    const int jt  = blockIdx.y;   // 0..31
    const int b0  = mt * 64, j0 = jt * 16;

    const int rb = (t + 2) % 3, wb = t % 3;
    const float* __restrict__ hprevD = d_h[rb] + (l * 2 + dir) * Bq * Hh;
    float* __restrict__       houtD  = d_h[wb] + (l * 2 + dir) * Bq * Hh;
    float* __restrict__       cstD   = d_c     + (l * 2 + dir) * Bq * Hh;
    const float* __restrict__ xbase  = (KIN == Ee) ? (d_x0 + t * Bq * Ee)
                                                   : (d_h[wb] + (l - 1) * 2 * Bq * Hh);
    const float* __restrict__ WihD   = (KIN == Ee) ? (d_Wih0 + dir * G4 * Ee)
                                                   : (d_WihL + ((l - 1) * 2 + dir) * G4 * 1024);
    const float* __restrict__ WhhD   = (KIN == Ee) ? (d_Whh0 + dir * G4 * Hh)
                                                   : (d_WhhL + ((l - 1) * 2 + dir) * G4 * Hh);

    // ---- hoisted cp.async geometry: 128 threads cover A(64rows x 4grps)/2 + B/2 per q ----
    const int lrow = tid >> 2, lgrp = tid & 3;
    uint32_t aSm[2], bSm[2];
    int aRow[2], bIh[2], bHh[2];
    #pragma unroll
    for (int q = 0; q < 2; ++q) {
        int row = lrow + q * 32;
        uint32_t sw = ((lgrp ^ (row & 3)) << 2);
        aSm[q]  = row * 16 + sw;
        bSm[q]  = row * 16 + sw;
        aRow[q] = b0 + row;
        int wrow = (row >> 4) * Hh + j0 + (row & 15);
        bIh[q]  = wrow * KIN + lgrp * 4;
        bHh[q]  = wrow * Hh + lgrp * 4;
    }

    auto load_stage = [&](int it, int buf) {
        const int k0 = it * 16;
        const int kk = k0 + lgrp * 4;
        float* sA = smem + buf * 2048;
        float* sB = sA + 1024;
        if (kk < KIN) {
            const float* ab = (KIN == Ee) ? xbase : (xbase + (kk >> 9) * Bq * Hh);
            const int ks = (KIN == Ee) ? kk : (kk & 511);
            const int as = (KIN == Ee) ? Ee : Hh;
            #pragma unroll
            for (int q = 0; q < 2; ++q) cp16(&sA[aSm[q]], ab + aRow[q] * as + ks);
            #pragma unroll
            for (int q = 0; q < 2; ++q) cp16(&sB[bSm[q]], WihD + bIh[q] + k0);
        } else {
            const int ko = kk - KIN;
            #pragma unroll
            for (int q = 0; q < 2; ++q) cp16(&sA[aSm[q]], hprevD + aRow[q] * Hh + ko);
            #pragma unroll
            for (int q = 0; q < 2; ++q) cp16(&sB[bSm[q]], WhhD + bHh[q] + (k0 - KIN));
        }
        cp_commit();
    };

    const int lane = tid & 31, wid = tid >> 5;
    const int wm = wid & 1, wn = wid >> 1;     // 2x2 warp grid, 32x32 warp tile
    const int g = lane >> 2, tg = lane & 3;

    // hoisted fragment smem offsets (floats, stage-relative)
    const uint32_t asw = ((tg ^ (g & 3)) << 2);
    uint32_t aOff[2][2], bOff[4];
    #pragma unroll
    for (int mi = 0; mi < 2; ++mi) {
        int r = wm * 32 + mi * 16 + g;
        aOff[mi][0] = r * 16 + asw;
        aOff[mi][1] = (r + 8) * 16 + asw;
    }
    #pragma unroll
    for (int ni = 0; ni < 4; ++ni) {
        int n = wn * 32 + ni * 8 + g;
        bOff[ni] = 1024 + n * 16 + ((tg ^ (n & 3)) << 2);
    }

    float acc[2][4][4];
    #pragma unroll
    for (int i = 0; i < 2; i++)
        #pragma unroll
        for (int j = 0; j < 4; j++)
            #pragma unroll
            for (int k = 0; k < 4; k++) acc[i][j][k] = 0.f;

    load_stage(0, 0);
    if (NIT > 1) load_stage(1, 1);
    int rdOff = 0, ldBuf = 2;   // rotating stage offsets (no div/mod)
    for (int it = 0; it < NIT; ++it) {
        if (it + 1 < NIT) cp_wait<1>();   // stage it landed (it+1 may fly)
        else              cp_wait<0>();
        __syncthreads();                  // also: all warps done reading stage (it+2)%3 (iter it-1)
        if (it + 2 < NIT) {
            load_stage(it + 2, ldBuf);
            if (++ldBuf == 3) ldBuf = 0;
        }
        const float* A = smem + rdOff;
        if ((rdOff += 2048) == 6144) rdOff = 0;

        float4 bv[4];
        #pragma unroll
        for (int ni = 0; ni < 4; ++ni)
            bv[ni] = *reinterpret_cast<const float4*>(A + bOff[ni]);
        #pragma unroll
        for (int mi = 0; mi < 2; ++mi) {
            float4 a0 = *reinterpret_cast<const float4*>(A + aOff[mi][0]);
            float4 a1 = *reinterpret_cast<const float4*>(A + aOff[mi][1]);
            #pragma unroll
            for (int ni = 0; ni < 4; ++ni) {
                mma_tf32(acc[mi][ni],
                         __float_as_uint(a0.x), __float_as_uint(a1.x),
                         __float_as_uint(a0.y), __float_as_uint(a1.y),
                         __float_as_uint(bv[ni].x), __float_as_uint(bv[ni].y));
                mma_tf32(acc[mi][ni],
                         __float_as_uint(a0.z), __float_as_uint(a1.z),
                         __float_as_uint(a0.w), __float_as_uint(a1.w),
                         __float_as_uint(bv[ni].z), __float_as_uint(bv[ni].w));
            }
        }
    }
    __syncthreads();   // all reads of stage buffers done before reuse as gt

    // ---- epilogue: restage gates to smem gt[64][80] ----
    float* gt = smem;
    #pragma unroll
    for (int mi = 0; mi < 2; ++mi)
        #pragma unroll
        for (int ni = 0; ni < 4; ++ni) {
            int r  = wm * 32 + mi * 16 + g;
            int cc = wn * 32 + ni * 8 + 2 * tg;
            gt[r * 80 + cc]           = acc[mi][ni][0];
            gt[r * 80 + cc + 1]       = acc[mi][ni][1];
            gt[(r + 8) * 80 + cc]     = acc[mi][ni][2];
            gt[(r + 8) * 80 + cc + 1] = acc[mi][ni][3];
        }
    __syncthreads();

    // elementwise LSTM cell update: 64 rows x 16 units, 8 cells/thread
    const int jj = tid & 15;           // unit within tile
    const int rbase = tid >> 4;        // 0..7
    const float* biasD = d_bias + (l * 2 + dir) * G4;
    const int j = j0 + jj;
    const float bi = biasD[0 * Hh + j];
    const float bf = biasD[1 * Hh + j];
    const float bg = biasD[2 * Hh + j];
    const float bo = biasD[3 * Hh + j];
    const int jp = j0 + (((jj & 3) << 2) | (jj >> 2));   // perm16'd h storage position
    #pragma unroll
    for (int q = 0; q < 8; ++q) {
        int row = rbase + q * 8;       // 0..63
        int b = b0 + row;
        float gi = gt[row * 80 +  0 + jj] + bi;
        float gf = gt[row * 80 + 16 + jj] + bf;
        float gg = gt[row * 80 + 32 + jj] + bg;
        float go = gt[row * 80 + 48 + jj] + bo;
        float i_ = sigf(gi), f_ = sigf(gf), g_ = tanhf(gg), o_ = sigf(go);
        float cn = fmaf(f_, cstD[b * Hh + j], i_ * g_);
        cstD[b * Hh + j]   = cn;
        houtD[b * Hh + jp] = tf32r(o_ * tanhf(cn));   // permuted store; tf32 pre-round (rna)
    }
}

// ---------------- wavefront kernel ----------------
// grid = (4 mtiles, 32 jtiles, ncells*2); blockIdx.z = (cell_idx << 1) | dir
__global__ __launch_bounds__(128, 7) void lstm_wave(int w, int lmin) {
    __shared__ __align__(16) float smem[6144];   // 3 stages x 2048 floats = 24 KB
    const int cell = blockIdx.z >> 1;
    const int dir  = blockIdx.z & 1;
    const int l    = lmin + cell;
    const int t    = w - l;
    if (t < 0 || t >= Tn) return;
    if (l == 0) lstm_cell<Ee>(t, 0, dir, smem);
    else        lstm_cell<1024>(t, l, dir, smem);
}

// ---------------- final FC + softmax ----------------
__global__ __launch_bounds__(256) void fc_softmax(const float* __restrict__ fcw,
                                                  const float* __restrict__ fcb,
                                                  float* __restrict__ out) {
    const int b = blockIdx.x;
    const int tid = threadIdx.x, lane = tid & 31, w = tid >> 5;
    __shared__ float sv[64];
    const float* __restrict__ hf = d_h[(Tn - 1) % 3];   // t=127 wrote ring slot 1
    float acc[8] = {0, 0, 0, 0, 0, 0, 0, 0};
    for (int k = lane; k < 8192; k += 32) {
        int s = k >> 10, r = k & 1023, j = r & 511;
        float hv = (r & 512) ? d_c[(s * Bq + b) * Hh + j]
                             : hf[(s * Bq + b) * Hh + perm16(j)];   // h stored permuted
        #pragma unroll
        for (int q = 0; q < 8; ++q)
            acc[q] = fmaf(hv, fcw[(w * 8 + q) * 8192 + k], acc[q]);
    }
    #pragma unroll
    for (int q = 0; q < 8; ++q) {
        float v = acc[q];
        #pragma unroll
        for (int off = 16; off; off >>= 1) v += __shfl_xor_sync(0xffffffffu, v, off);
        if (lane == 0) sv[w * 8 + q] = v + fcb[w * 8 + q];
    }
    __syncthreads();
    if (tid < 32) {
        float v0 = sv[tid], v1 = sv[tid + 32];
        float m = fmaxf(v0, v1);
        #pragma unroll
        for (int off = 16; off; off >>= 1) m = fmaxf(m, __shfl_xor_sync(0xffffffffu, m, off));
        float e0 = expf(v0 - m), e1 = expf(v1 - m);
        float s = e0 + e1;
        #pragma unroll
        for (int off = 16; off; off >>= 1) s += __shfl_xor_sync(0xffffffffu, s, off);
        float inv = 1.0f / s;
        out[b * 64 + tid]      = e0 * inv;
        out[b * 64 + 32 + tid] = e1 * inv;
    }
}

// ---------------- launch ----------------
extern "C" void kernel_launch(void* const* d_in, const int* in_sizes, int n_in,
                              void* d_out, int out_size) {
    const int*   tokens = (const int*)  d_in[0];
    const float* embed  = (const float*)d_in[1];
    const float* Wih0   = (const float*)d_in[2];
    const float* Whh0   = (const float*)d_in[3];
    const float* bih0   = (const float*)d_in[4];
    const float* bhh0   = (const float*)d_in[5];
    const float* Wih    = (const float*)d_in[6];
    const float* Whh    = (const float*)d_in[7];
    const float* bih    = (const float*)d_in[8];
    const float* bhh    = (const float*)d_in[9];
    const float* fcw    = (const float*)d_in[10];
    const float* fcb    = (const float*)d_in[11];
    float*       out    = (float*)d_out;

    init_kernel<<<512, 256>>>(tokens, embed, Wih0, Whh0, bih0, bhh0, Wih, Whh, bih, bhh);

    // wavefront schedule: cells (t, l) with t + l == w are independent
    for (int w = 0; w <= (Tn - 1) + (Ln - 1); ++w) {
        int lmin = max(0, w - (Tn - 1));
        int lmax = min(Ln - 1, w);
        int ncells = lmax - lmin + 1;
        dim3 grid(4, 32, ncells * 2);
        lstm_wave<<<grid, 128>>>(w, lmin);
    }
    fc_softmax<<<Bq, 256>>>(fcw, fcb, out);
}